// round 13
// baseline (speedup 1.0000x reference)
#include <cuda_runtime.h>

typedef unsigned long long ull;

#define STR 66
#define NCTA 2048
#define CBUF_ULL (11 * 1024)
#define SMEM_BYTES (CBUF_ULL * 8 + 5 * 32 * 8 * 16 + 256 * STR * 4)

__device__ __forceinline__ ull pack2f(float lo, float hi) {
    ull r;
    asm("mov.b64 %0,{%1,%2};" : "=l"(r)
        : "r"(__float_as_uint(lo)), "r"(__float_as_uint(hi)));
    return r;
}
__device__ __forceinline__ void fma2(ull& d, ull a, ull b) {
    asm("fma.rn.f32x2 %0,%1,%2,%0;" : "+l"(d) : "l"(a), "l"(b));
}
__device__ __forceinline__ float2 up2(ull v) {
    unsigned lo, hi;
    asm("mov.b64 {%0,%1},%2;" : "=r"(lo), "=r"(hi) : "l"(v));
    return make_float2(__uint_as_float(lo), __uint_as_float(hi));
}

__global__ void __launch_bounds__(256, 1)
tp_kernel(const float* __restrict__ x1, const float* __restrict__ x2,
          const float* __restrict__ w000, const float* __restrict__ w011,
          const float* __restrict__ w101, const float* __restrict__ w110,
          const float* __restrict__ w111, float* __restrict__ out)
{
    const float A  = 0.02209708691207961f;   // 1/sqrt(2048)
    const float R3 = 0.5773502691896258f;    // 1/sqrt(3)

    extern __shared__ char sm[];
    ull*    cbuf = (ull*)sm;                                  // [11][32u*32p] f32x2
    float4* wbuf = (float4*)(sm + CBUF_ULL * 8);              // [5][32u][8] float4
    float*  stg  = (float*)(sm + CBUF_ULL * 8 + 5 * 32 * 8 * 16);
    float*  x1s_s = stg;                // [32][STR]
    float*  x1v_s = stg + 32 * STR;     // [96][STR]
    float*  s2_s  = stg + 128 * STR;    // [32][STR]  A*x2s
    float*  v2_s  = stg + 160 * STR;    // [96][STR]  A*x2v

    const int tid = threadIdx.x, lane = tid & 31, warp = tid >> 5;
    const int zb = blockIdx.x * 64;
    const int pm = tid >> 3;   // row pair 0..31
    const int wq = tid & 7;    // w-quad 0..7

    // ---- stage inputs, z-fastest ----
    for (int idx = tid; idx < 64 * 32; idx += 256) {
        int z = idx >> 5, c4 = idx & 31;
        float4 a = ((const float4*)x1)[(size_t)(zb + z) * 32 + c4];
        float4 b = ((const float4*)x2)[(size_t)(zb + z) * 32 + c4];
        float av[4] = {a.x, a.y, a.z, a.w}, bv[4] = {b.x, b.y, b.z, b.w};
        #pragma unroll
        for (int e = 0; e < 4; e++) {
            int col = c4 * 4 + e;
            if (col < 32) { x1s_s[col * STR + z] = av[e]; s2_s[col * STR + z] = A * bv[e]; }
            else          { x1v_s[(col - 32) * STR + z] = av[e]; v2_s[(col - 32) * STR + z] = A * bv[e]; }
        }
    }
    __syncthreads();

    ull a0[4], a1[4][3], a2[4][3];
    #pragma unroll
    for (int j = 0; j < 4; j++) {
        a0[j] = 0ull;
        #pragma unroll
        for (int d = 0; d < 3; d++) { a1[j][d] = 0ull; a2[j][d] = 0ull; }
    }

    const float* wp[5] = {w000, w110, w011, w101, w111};

    for (int v = 0; v < 32; v++) {
        // prefetch weight slices for this v (global/L2, before barrier)
        float4 wr[5];
        #pragma unroll
        for (int m = 0; m < 5; m++)
            wr[m] = *(const float4*)(wp[m] + pm * 1024 + v * 32 + wq * 4);

        if (v) __syncthreads();   // prior readers of cbuf/wbuf done

        #pragma unroll
        for (int m = 0; m < 5; m++)
            wbuf[(m * 32 + pm) * 8 + wq] = wr[m];

        // ---- coefficient planes for this v: u = warp+8k, pair p = lane ----
        {
            int p = lane;
            float2 bs = *(const float2*)&s2_s[v * STR + 2 * p];
            float2 b0 = *(const float2*)&v2_s[(v * 3 + 0) * STR + 2 * p];
            float2 b1 = *(const float2*)&v2_s[(v * 3 + 1) * STR + 2 * p];
            float2 b2 = *(const float2*)&v2_s[(v * 3 + 2) * STR + 2 * p];
            #pragma unroll
            for (int k = 0; k < 4; k++) {
                int u = warp + 8 * k;
                float2 as = *(const float2*)&x1s_s[u * STR + 2 * p];
                float2 u0 = *(const float2*)&x1v_s[(u * 3 + 0) * STR + 2 * p];
                float2 u1 = *(const float2*)&x1v_s[(u * 3 + 1) * STR + 2 * p];
                float2 u2 = *(const float2*)&x1v_s[(u * 3 + 2) * STR + 2 * p];
                int ci = u * 32 + p;
                cbuf[            ci] = pack2f(as.x * bs.x, as.y * bs.y);
                cbuf[ 1024     + ci] = pack2f(R3 * (u0.x * b0.x + u1.x * b1.x + u2.x * b2.x),
                                              R3 * (u0.y * b0.y + u1.y * b1.y + u2.y * b2.y));
                cbuf[ 2 * 1024 + ci] = pack2f(as.x * b0.x, as.y * b0.y);
                cbuf[ 3 * 1024 + ci] = pack2f(as.x * b1.x, as.y * b1.y);
                cbuf[ 4 * 1024 + ci] = pack2f(as.x * b2.x, as.y * b2.y);
                cbuf[ 5 * 1024 + ci] = pack2f(u0.x * bs.x, u0.y * bs.y);
                cbuf[ 6 * 1024 + ci] = pack2f(u1.x * bs.x, u1.y * bs.y);
                cbuf[ 7 * 1024 + ci] = pack2f(u2.x * bs.x, u2.y * bs.y);
                cbuf[ 8 * 1024 + ci] = pack2f(u1.x * b2.x - u2.x * b1.x,
                                              u1.y * b2.y - u2.y * b1.y);
                cbuf[ 9 * 1024 + ci] = pack2f(u2.x * b0.x - u0.x * b2.x,
                                              u2.y * b0.y - u0.y * b2.y);
                cbuf[10 * 1024 + ci] = pack2f(u0.x * b1.x - u1.x * b0.x,
                                              u0.y * b1.y - u1.y * b0.y);
            }
        }
        __syncthreads();

        // ---- main accumulation over u ----
        #pragma unroll 2
        for (int u = 0; u < 32; u++) {
            const ull* cb = cbuf + u * 32 + pm;
            ull c000 = cb[0], c110 = cb[1024];
            ull c011[3] = {cb[2048], cb[3072], cb[4096]};
            ull c101[3] = {cb[5120], cb[6144], cb[7168]};
            ull c111[3] = {cb[8192], cb[9216], cb[10240]};
            const float4* wb = wbuf + u * 8 + wq;
            float4 W0 = wb[0], W1 = wb[256], W2 = wb[512], W3 = wb[768], W4 = wb[1024];
            float f0[4] = {W0.x, W0.y, W0.z, W0.w};
            float f1[4] = {W1.x, W1.y, W1.z, W1.w};
            float f2[4] = {W2.x, W2.y, W2.z, W2.w};
            float f3[4] = {W3.x, W3.y, W3.z, W3.w};
            float f4[4] = {W4.x, W4.y, W4.z, W4.w};
            #pragma unroll
            for (int j = 0; j < 4; j++) {
                ull d0 = pack2f(f0[j], f0[j]), d1 = pack2f(f1[j], f1[j]);
                ull d2 = pack2f(f2[j], f2[j]), d3 = pack2f(f3[j], f3[j]);
                ull d4 = pack2f(f4[j], f4[j]);
                fma2(a0[j], c000, d0);
                fma2(a0[j], c110, d1);
                #pragma unroll
                for (int d = 0; d < 3; d++) {
                    fma2(a1[j][d], c011[d], d2);
                    fma2(a1[j][d], c101[d], d3);
                    fma2(a2[j][d], c111[d], d4);
                }
            }
        }
    }

    // ---- store: rows 2*pm, 2*pm+1; w = 4*wq..4*wq+3 ----
    #pragma unroll
    for (int r = 0; r < 2; r++) {
        float* o = out + (size_t)(zb + 2 * pm + r) * 224;
        float o0[4], o1[12], o2[12];
        #pragma unroll
        for (int j = 0; j < 4; j++) {
            float2 t = up2(a0[j]); o0[j] = r ? t.y : t.x;
            #pragma unroll
            for (int d = 0; d < 3; d++) {
                float2 t1 = up2(a1[j][d]); o1[j * 3 + d] = r ? t1.y : t1.x;
                float2 t2 = up2(a2[j][d]); o2[j * 3 + d] = r ? t2.y : t2.x;
            }
        }
        ((float4*)o)[wq] = make_float4(o0[0], o0[1], o0[2], o0[3]);
        float4* q1 = (float4*)(o + 32 + 12 * wq);
        q1[0] = make_float4(o1[0], o1[1], o1[2],  o1[3]);
        q1[1] = make_float4(o1[4], o1[5], o1[6],  o1[7]);
        q1[2] = make_float4(o1[8], o1[9], o1[10], o1[11]);
        float4* q2 = (float4*)(o + 128 + 12 * wq);
        q2[0] = make_float4(o2[0], o2[1], o2[2],  o2[3]);
        q2[1] = make_float4(o2[4], o2[5], o2[6],  o2[7]);
        q2[2] = make_float4(o2[8], o2[9], o2[10], o2[11]);
    }
}

extern "C" void kernel_launch(void* const* d_in, const int* in_sizes, int n_in,
                              void* d_out, int out_size) {
    (void)in_sizes; (void)n_in; (void)out_size;
    cudaFuncSetAttribute(tp_kernel, cudaFuncAttributeMaxDynamicSharedMemorySize, SMEM_BYTES);
    tp_kernel<<<NCTA, 256, SMEM_BYTES>>>(
        (const float*)d_in[0],   // x1
        (const float*)d_in[1],   // x2
        (const float*)d_in[2],   // w000
        (const float*)d_in[3],   // w011
        (const float*)d_in[4],   // w101
        (const float*)d_in[5],   // w110
        (const float*)d_in[6],   // w111
        (float*)d_out);
}

// round 14
// speedup vs baseline: 1.0008x; 1.0008x over previous
#include <cuda_runtime.h>

typedef unsigned long long ull;

#define STR 66
#define NCTA 2048
#define CBUF_ULL (11 * 1024)
#define SMEM_BYTES (CBUF_ULL * 8 + 5 * 32 * 8 * 16 + 256 * STR * 4)

__device__ __forceinline__ ull pack2f(float lo, float hi) {
    ull r;
    asm("mov.b64 %0,{%1,%2};" : "=l"(r)
        : "r"(__float_as_uint(lo)), "r"(__float_as_uint(hi)));
    return r;
}
__device__ __forceinline__ void fma2(ull& d, ull a, ull b) {
    asm("fma.rn.f32x2 %0,%1,%2,%0;" : "+l"(d) : "l"(a), "l"(b));
}
__device__ __forceinline__ float2 up2(ull v) {
    unsigned lo, hi;
    asm("mov.b64 {%0,%1},%2;" : "=r"(lo), "=r"(hi) : "l"(v));
    return make_float2(__uint_as_float(lo), __uint_as_float(hi));
}

__global__ void __launch_bounds__(256, 1)
tp_kernel(const float* __restrict__ x1, const float* __restrict__ x2,
          const float* __restrict__ w000, const float* __restrict__ w011,
          const float* __restrict__ w101, const float* __restrict__ w110,
          const float* __restrict__ w111, float* __restrict__ out)
{
    const float A  = 0.02209708691207961f;   // 1/sqrt(2048)
    const float R3 = 0.5773502691896258f;    // 1/sqrt(3)

    extern __shared__ char sm[];
    ull*    cbuf = (ull*)sm;                                  // [11][32u*32p] f32x2
    float4* wbuf = (float4*)(sm + CBUF_ULL * 8);              // [5][32u][8] float4
    float*  stg  = (float*)(sm + CBUF_ULL * 8 + 5 * 32 * 8 * 16);
    float*  x1s_s = stg;                // [32][STR]
    float*  x1v_s = stg + 32 * STR;     // [96][STR]
    float*  s2_s  = stg + 128 * STR;    // [32][STR]  A*x2s
    float*  v2_s  = stg + 160 * STR;    // [96][STR]  A*x2v

    const int tid = threadIdx.x, lane = tid & 31, warp = tid >> 5;
    const int zb = blockIdx.x * 64;
    const int pm = tid >> 3;   // row pair 0..31
    const int wq = tid & 7;    // w-quad 0..7

    // ---- stage inputs, z-fastest ----
    for (int idx = tid; idx < 64 * 32; idx += 256) {
        int z = idx >> 5, c4 = idx & 31;
        float4 a = ((const float4*)x1)[(size_t)(zb + z) * 32 + c4];
        float4 b = ((const float4*)x2)[(size_t)(zb + z) * 32 + c4];
        float av[4] = {a.x, a.y, a.z, a.w}, bv[4] = {b.x, b.y, b.z, b.w};
        #pragma unroll
        for (int e = 0; e < 4; e++) {
            int col = c4 * 4 + e;
            if (col < 32) { x1s_s[col * STR + z] = av[e]; s2_s[col * STR + z] = A * bv[e]; }
            else          { x1v_s[(col - 32) * STR + z] = av[e]; v2_s[(col - 32) * STR + z] = A * bv[e]; }
        }
    }
    __syncthreads();

    ull a0[4], a1[4][3], a2[4][3];
    #pragma unroll
    for (int j = 0; j < 4; j++) {
        a0[j] = 0ull;
        #pragma unroll
        for (int d = 0; d < 3; d++) { a1[j][d] = 0ull; a2[j][d] = 0ull; }
    }

    const float* wp[5] = {w000, w110, w011, w101, w111};

    for (int v = 0; v < 32; v++) {
        // prefetch weight slices for this v (global/L2, before barrier)
        float4 wr[5];
        #pragma unroll
        for (int m = 0; m < 5; m++)
            wr[m] = *(const float4*)(wp[m] + pm * 1024 + v * 32 + wq * 4);

        if (v) __syncthreads();   // prior readers of cbuf/wbuf done

        #pragma unroll
        for (int m = 0; m < 5; m++)
            wbuf[(m * 32 + pm) * 8 + wq] = wr[m];

        // ---- coefficient planes for this v: u = warp+8k, pair p = lane ----
        {
            int p = lane;
            float2 bs = *(const float2*)&s2_s[v * STR + 2 * p];
            float2 b0 = *(const float2*)&v2_s[(v * 3 + 0) * STR + 2 * p];
            float2 b1 = *(const float2*)&v2_s[(v * 3 + 1) * STR + 2 * p];
            float2 b2 = *(const float2*)&v2_s[(v * 3 + 2) * STR + 2 * p];
            #pragma unroll
            for (int k = 0; k < 4; k++) {
                int u = warp + 8 * k;
                float2 as = *(const float2*)&x1s_s[u * STR + 2 * p];
                float2 u0 = *(const float2*)&x1v_s[(u * 3 + 0) * STR + 2 * p];
                float2 u1 = *(const float2*)&x1v_s[(u * 3 + 1) * STR + 2 * p];
                float2 u2 = *(const float2*)&x1v_s[(u * 3 + 2) * STR + 2 * p];
                int ci = u * 32 + p;
                cbuf[            ci] = pack2f(as.x * bs.x, as.y * bs.y);
                cbuf[ 1024     + ci] = pack2f(R3 * (u0.x * b0.x + u1.x * b1.x + u2.x * b2.x),
                                              R3 * (u0.y * b0.y + u1.y * b1.y + u2.y * b2.y));
                cbuf[ 2 * 1024 + ci] = pack2f(as.x * b0.x, as.y * b0.y);
                cbuf[ 3 * 1024 + ci] = pack2f(as.x * b1.x, as.y * b1.y);
                cbuf[ 4 * 1024 + ci] = pack2f(as.x * b2.x, as.y * b2.y);
                cbuf[ 5 * 1024 + ci] = pack2f(u0.x * bs.x, u0.y * bs.y);
                cbuf[ 6 * 1024 + ci] = pack2f(u1.x * bs.x, u1.y * bs.y);
                cbuf[ 7 * 1024 + ci] = pack2f(u2.x * bs.x, u2.y * bs.y);
                cbuf[ 8 * 1024 + ci] = pack2f(u1.x * b2.x - u2.x * b1.x,
                                              u1.y * b2.y - u2.y * b1.y);
                cbuf[ 9 * 1024 + ci] = pack2f(u2.x * b0.x - u0.x * b2.x,
                                              u2.y * b0.y - u0.y * b2.y);
                cbuf[10 * 1024 + ci] = pack2f(u0.x * b1.x - u1.x * b0.x,
                                              u0.y * b1.y - u1.y * b0.y);
            }
        }
        __syncthreads();

        // ---- main accumulation over u ----
        #pragma unroll 2
        for (int u = 0; u < 32; u++) {
            const ull* cb = cbuf + u * 32 + pm;
            ull c000 = cb[0], c110 = cb[1024];
            ull c011[3] = {cb[2048], cb[3072], cb[4096]};
            ull c101[3] = {cb[5120], cb[6144], cb[7168]};
            ull c111[3] = {cb[8192], cb[9216], cb[10240]};
            const float4* wb = wbuf + u * 8 + wq;
            float4 W0 = wb[0], W1 = wb[256], W2 = wb[512], W3 = wb[768], W4 = wb[1024];
            float f0[4] = {W0.x, W0.y, W0.z, W0.w};
            float f1[4] = {W1.x, W1.y, W1.z, W1.w};
            float f2[4] = {W2.x, W2.y, W2.z, W2.w};
            float f3[4] = {W3.x, W3.y, W3.z, W3.w};
            float f4[4] = {W4.x, W4.y, W4.z, W4.w};
            #pragma unroll
            for (int j = 0; j < 4; j++) {
                ull d0 = pack2f(f0[j], f0[j]), d1 = pack2f(f1[j], f1[j]);
                ull d2 = pack2f(f2[j], f2[j]), d3 = pack2f(f3[j], f3[j]);
                ull d4 = pack2f(f4[j], f4[j]);
                fma2(a0[j], c000, d0);
                fma2(a0[j], c110, d1);
                #pragma unroll
                for (int d = 0; d < 3; d++) {
                    fma2(a1[j][d], c011[d], d2);
                    fma2(a1[j][d], c101[d], d3);
                    fma2(a2[j][d], c111[d], d4);
                }
            }
        }
    }

    // ---- store: rows 2*pm, 2*pm+1; w = 4*wq..4*wq+3 ----
    #pragma unroll
    for (int r = 0; r < 2; r++) {
        float* o = out + (size_t)(zb + 2 * pm + r) * 224;
        float o0[4], o1[12], o2[12];
        #pragma unroll
        for (int j = 0; j < 4; j++) {
            float2 t = up2(a0[j]); o0[j] = r ? t.y : t.x;
            #pragma unroll
            for (int d = 0; d < 3; d++) {
                float2 t1 = up2(a1[j][d]); o1[j * 3 + d] = r ? t1.y : t1.x;
                float2 t2 = up2(a2[j][d]); o2[j * 3 + d] = r ? t2.y : t2.x;
            }
        }
        ((float4*)o)[wq] = make_float4(o0[0], o0[1], o0[2], o0[3]);
        float4* q1 = (float4*)(o + 32 + 12 * wq);
        q1[0] = make_float4(o1[0], o1[1], o1[2],  o1[3]);
        q1[1] = make_float4(o1[4], o1[5], o1[6],  o1[7]);
        q1[2] = make_float4(o1[8], o1[9], o1[10], o1[11]);
        float4* q2 = (float4*)(o + 128 + 12 * wq);
        q2[0] = make_float4(o2[0], o2[1], o2[2],  o2[3]);
        q2[1] = make_float4(o2[4], o2[5], o2[6],  o2[7]);
        q2[2] = make_float4(o2[8], o2[9], o2[10], o2[11]);
    }
}

extern "C" void kernel_launch(void* const* d_in, const int* in_sizes, int n_in,
                              void* d_out, int out_size) {
    (void)in_sizes; (void)n_in; (void)out_size;
    cudaFuncSetAttribute(tp_kernel, cudaFuncAttributeMaxDynamicSharedMemorySize, SMEM_BYTES);
    tp_kernel<<<NCTA, 256, SMEM_BYTES>>>(
        (const float*)d_in[0],   // x1
        (const float*)d_in[1],   // x2
        (const float*)d_in[2],   // w000
        (const float*)d_in[3],   // w011
        (const float*)d_in[4],   // w101
        (const float*)d_in[5],   // w110
        (const float*)d_in[6],   // w111
        (float*)d_out);
}

// round 15
// speedup vs baseline: 1.0020x; 1.0012x over previous
#include <cuda_runtime.h>

typedef unsigned long long ull;

#define STR 66
#define NCTA 2048
#define CBUF_ULL (11 * 1024)
#define SMEM_BYTES (CBUF_ULL * 8 + 5 * 32 * 8 * 16 + 256 * STR * 4)

__device__ __forceinline__ ull pack2f(float lo, float hi) {
    ull r;
    asm("mov.b64 %0,{%1,%2};" : "=l"(r)
        : "r"(__float_as_uint(lo)), "r"(__float_as_uint(hi)));
    return r;
}
__device__ __forceinline__ void fma2(ull& d, ull a, ull b) {
    asm("fma.rn.f32x2 %0,%1,%2,%0;" : "+l"(d) : "l"(a), "l"(b));
}
__device__ __forceinline__ float2 up2(ull v) {
    unsigned lo, hi;
    asm("mov.b64 {%0,%1},%2;" : "=r"(lo), "=r"(hi) : "l"(v));
    return make_float2(__uint_as_float(lo), __uint_as_float(hi));
}

__global__ void __launch_bounds__(256, 1)
tp_kernel(const float* __restrict__ x1, const float* __restrict__ x2,
          const float* __restrict__ w000, const float* __restrict__ w011,
          const float* __restrict__ w101, const float* __restrict__ w110,
          const float* __restrict__ w111, float* __restrict__ out)
{
    const float A  = 0.02209708691207961f;   // 1/sqrt(2048)
    const float R3 = 0.5773502691896258f;    // 1/sqrt(3)

    extern __shared__ char sm[];
    ull*    cbuf = (ull*)sm;                                  // [11][32u*32p] f32x2
    float4* wbuf = (float4*)(sm + CBUF_ULL * 8);              // [5][32u][8] float4
    float*  stg  = (float*)(sm + CBUF_ULL * 8 + 5 * 32 * 8 * 16);
    float*  x1s_s = stg;                // [32][STR]
    float*  x1v_s = stg + 32 * STR;     // [96][STR]
    float*  s2_s  = stg + 128 * STR;    // [32][STR]  A*x2s
    float*  v2_s  = stg + 160 * STR;    // [96][STR]  A*x2v

    const int tid = threadIdx.x, lane = tid & 31, warp = tid >> 5;
    const int zb = blockIdx.x * 64;
    const int pm = tid >> 3;   // row pair 0..31
    const int wq = tid & 7;    // w-quad 0..7

    // ---- stage inputs, z-fastest ----
    for (int idx = tid; idx < 64 * 32; idx += 256) {
        int z = idx >> 5, c4 = idx & 31;
        float4 a = ((const float4*)x1)[(size_t)(zb + z) * 32 + c4];
        float4 b = ((const float4*)x2)[(size_t)(zb + z) * 32 + c4];
        float av[4] = {a.x, a.y, a.z, a.w}, bv[4] = {b.x, b.y, b.z, b.w};
        #pragma unroll
        for (int e = 0; e < 4; e++) {
            int col = c4 * 4 + e;
            if (col < 32) { x1s_s[col * STR + z] = av[e]; s2_s[col * STR + z] = A * bv[e]; }
            else          { x1v_s[(col - 32) * STR + z] = av[e]; v2_s[(col - 32) * STR + z] = A * bv[e]; }
        }
    }
    __syncthreads();

    ull a0[4], a1[4][3], a2[4][3];
    #pragma unroll
    for (int j = 0; j < 4; j++) {
        a0[j] = 0ull;
        #pragma unroll
        for (int d = 0; d < 3; d++) { a1[j][d] = 0ull; a2[j][d] = 0ull; }
    }

    const float* wp[5] = {w000, w110, w011, w101, w111};

    for (int v = 0; v < 32; v++) {
        // prefetch weight slices for this v (global/L2, before barrier)
        float4 wr[5];
        #pragma unroll
        for (int m = 0; m < 5; m++)
            wr[m] = *(const float4*)(wp[m] + pm * 1024 + v * 32 + wq * 4);

        if (v) __syncthreads();   // prior readers of cbuf/wbuf done

        #pragma unroll
        for (int m = 0; m < 5; m++)
            wbuf[(m * 32 + pm) * 8 + wq] = wr[m];

        // ---- coefficient planes for this v: u = warp+8k, pair p = lane ----
        {
            int p = lane;
            float2 bs = *(const float2*)&s2_s[v * STR + 2 * p];
            float2 b0 = *(const float2*)&v2_s[(v * 3 + 0) * STR + 2 * p];
            float2 b1 = *(const float2*)&v2_s[(v * 3 + 1) * STR + 2 * p];
            float2 b2 = *(const float2*)&v2_s[(v * 3 + 2) * STR + 2 * p];
            #pragma unroll
            for (int k = 0; k < 4; k++) {
                int u = warp + 8 * k;
                float2 as = *(const float2*)&x1s_s[u * STR + 2 * p];
                float2 u0 = *(const float2*)&x1v_s[(u * 3 + 0) * STR + 2 * p];
                float2 u1 = *(const float2*)&x1v_s[(u * 3 + 1) * STR + 2 * p];
                float2 u2 = *(const float2*)&x1v_s[(u * 3 + 2) * STR + 2 * p];
                int ci = u * 32 + p;
                cbuf[            ci] = pack2f(as.x * bs.x, as.y * bs.y);
                cbuf[ 1024     + ci] = pack2f(R3 * (u0.x * b0.x + u1.x * b1.x + u2.x * b2.x),
                                              R3 * (u0.y * b0.y + u1.y * b1.y + u2.y * b2.y));
                cbuf[ 2 * 1024 + ci] = pack2f(as.x * b0.x, as.y * b0.y);
                cbuf[ 3 * 1024 + ci] = pack2f(as.x * b1.x, as.y * b1.y);
                cbuf[ 4 * 1024 + ci] = pack2f(as.x * b2.x, as.y * b2.y);
                cbuf[ 5 * 1024 + ci] = pack2f(u0.x * bs.x, u0.y * bs.y);
                cbuf[ 6 * 1024 + ci] = pack2f(u1.x * bs.x, u1.y * bs.y);
                cbuf[ 7 * 1024 + ci] = pack2f(u2.x * bs.x, u2.y * bs.y);
                cbuf[ 8 * 1024 + ci] = pack2f(u1.x * b2.x - u2.x * b1.x,
                                              u1.y * b2.y - u2.y * b1.y);
                cbuf[ 9 * 1024 + ci] = pack2f(u2.x * b0.x - u0.x * b2.x,
                                              u2.y * b0.y - u0.y * b2.y);
                cbuf[10 * 1024 + ci] = pack2f(u0.x * b1.x - u1.x * b0.x,
                                              u0.y * b1.y - u1.y * b0.y);
            }
        }
        __syncthreads();

        // ---- main accumulation over u ----
        #pragma unroll 2
        for (int u = 0; u < 32; u++) {
            const ull* cb = cbuf + u * 32 + pm;
            ull c000 = cb[0], c110 = cb[1024];
            ull c011[3] = {cb[2048], cb[3072], cb[4096]};
            ull c101[3] = {cb[5120], cb[6144], cb[7168]};
            ull c111[3] = {cb[8192], cb[9216], cb[10240]};
            const float4* wb = wbuf + u * 8 + wq;
            float4 W0 = wb[0], W1 = wb[256], W2 = wb[512], W3 = wb[768], W4 = wb[1024];
            float f0[4] = {W0.x, W0.y, W0.z, W0.w};
            float f1[4] = {W1.x, W1.y, W1.z, W1.w};
            float f2[4] = {W2.x, W2.y, W2.z, W2.w};
            float f3[4] = {W3.x, W3.y, W3.z, W3.w};
            float f4[4] = {W4.x, W4.y, W4.z, W4.w};
            #pragma unroll
            for (int j = 0; j < 4; j++) {
                ull d0 = pack2f(f0[j], f0[j]), d1 = pack2f(f1[j], f1[j]);
                ull d2 = pack2f(f2[j], f2[j]), d3 = pack2f(f3[j], f3[j]);
                ull d4 = pack2f(f4[j], f4[j]);
                fma2(a0[j], c000, d0);
                fma2(a0[j], c110, d1);
                #pragma unroll
                for (int d = 0; d < 3; d++) {
                    fma2(a1[j][d], c011[d], d2);
                    fma2(a1[j][d], c101[d], d3);
                    fma2(a2[j][d], c111[d], d4);
                }
            }
        }
    }

    // ---- store: rows 2*pm, 2*pm+1; w = 4*wq..4*wq+3 ----
    #pragma unroll
    for (int r = 0; r < 2; r++) {
        float* o = out + (size_t)(zb + 2 * pm + r) * 224;
        float o0[4], o1[12], o2[12];
        #pragma unroll
        for (int j = 0; j < 4; j++) {
            float2 t = up2(a0[j]); o0[j] = r ? t.y : t.x;
            #pragma unroll
            for (int d = 0; d < 3; d++) {
                float2 t1 = up2(a1[j][d]); o1[j * 3 + d] = r ? t1.y : t1.x;
                float2 t2 = up2(a2[j][d]); o2[j * 3 + d] = r ? t2.y : t2.x;
            }
        }
        ((float4*)o)[wq] = make_float4(o0[0], o0[1], o0[2], o0[3]);
        float4* q1 = (float4*)(o + 32 + 12 * wq);
        q1[0] = make_float4(o1[0], o1[1], o1[2],  o1[3]);
        q1[1] = make_float4(o1[4], o1[5], o1[6],  o1[7]);
        q1[2] = make_float4(o1[8], o1[9], o1[10], o1[11]);
        float4* q2 = (float4*)(o + 128 + 12 * wq);
        q2[0] = make_float4(o2[0], o2[1], o2[2],  o2[3]);
        q2[1] = make_float4(o2[4], o2[5], o2[6],  o2[7]);
        q2[2] = make_float4(o2[8], o2[9], o2[10], o2[11]);
    }
}

extern "C" void kernel_launch(void* const* d_in, const int* in_sizes, int n_in,
                              void* d_out, int out_size) {
    (void)in_sizes; (void)n_in; (void)out_size;
    cudaFuncSetAttribute(tp_kernel, cudaFuncAttributeMaxDynamicSharedMemorySize, SMEM_BYTES);
    tp_kernel<<<NCTA, 256, SMEM_BYTES>>>(
        (const float*)d_in[0],   // x1
        (const float*)d_in[1],   // x2
        (const float*)d_in[2],   // w000
        (const float*)d_in[3],   // w011
        (const float*)d_in[4],   // w101
        (const float*)d_in[5],   // w110
        (const float*)d_in[6],   // w111
        (float*)d_out);
}

// round 16
// speedup vs baseline: 1.0024x; 1.0004x over previous
#include <cuda_runtime.h>

typedef unsigned long long ull;

#define STR 66
#define NCTA 2048
#define CBUF_ULL (11 * 1024)
#define SMEM_BYTES (CBUF_ULL * 8 + 5 * 32 * 8 * 16 + 256 * STR * 4)

__device__ __forceinline__ ull pack2f(float lo, float hi) {
    ull r;
    asm("mov.b64 %0,{%1,%2};" : "=l"(r)
        : "r"(__float_as_uint(lo)), "r"(__float_as_uint(hi)));
    return r;
}
__device__ __forceinline__ void fma2(ull& d, ull a, ull b) {
    asm("fma.rn.f32x2 %0,%1,%2,%0;" : "+l"(d) : "l"(a), "l"(b));
}
__device__ __forceinline__ float2 up2(ull v) {
    unsigned lo, hi;
    asm("mov.b64 {%0,%1},%2;" : "=r"(lo), "=r"(hi) : "l"(v));
    return make_float2(__uint_as_float(lo), __uint_as_float(hi));
}

__global__ void __launch_bounds__(256, 1)
tp_kernel(const float* __restrict__ x1, const float* __restrict__ x2,
          const float* __restrict__ w000, const float* __restrict__ w011,
          const float* __restrict__ w101, const float* __restrict__ w110,
          const float* __restrict__ w111, float* __restrict__ out)
{
    const float A  = 0.02209708691207961f;   // 1/sqrt(2048)
    const float R3 = 0.5773502691896258f;    // 1/sqrt(3)

    extern __shared__ char sm[];
    ull*    cbuf = (ull*)sm;                                  // [11][32u*32p] f32x2
    float4* wbuf = (float4*)(sm + CBUF_ULL * 8);              // [5][32u][8] float4
    float*  stg  = (float*)(sm + CBUF_ULL * 8 + 5 * 32 * 8 * 16);
    float*  x1s_s = stg;                // [32][STR]
    float*  x1v_s = stg + 32 * STR;     // [96][STR]
    float*  s2_s  = stg + 128 * STR;    // [32][STR]  A*x2s
    float*  v2_s  = stg + 160 * STR;    // [96][STR]  A*x2v

    const int tid = threadIdx.x, lane = tid & 31, warp = tid >> 5;
    const int zb = blockIdx.x * 64;
    const int pm = tid >> 3;   // row pair 0..31
    const int wq = tid & 7;    // w-quad 0..7

    // ---- stage inputs, z-fastest ----
    for (int idx = tid; idx < 64 * 32; idx += 256) {
        int z = idx >> 5, c4 = idx & 31;
        float4 a = ((const float4*)x1)[(size_t)(zb + z) * 32 + c4];
        float4 b = ((const float4*)x2)[(size_t)(zb + z) * 32 + c4];
        float av[4] = {a.x, a.y, a.z, a.w}, bv[4] = {b.x, b.y, b.z, b.w};
        #pragma unroll
        for (int e = 0; e < 4; e++) {
            int col = c4 * 4 + e;
            if (col < 32) { x1s_s[col * STR + z] = av[e]; s2_s[col * STR + z] = A * bv[e]; }
            else          { x1v_s[(col - 32) * STR + z] = av[e]; v2_s[(col - 32) * STR + z] = A * bv[e]; }
        }
    }
    __syncthreads();

    ull a0[4], a1[4][3], a2[4][3];
    #pragma unroll
    for (int j = 0; j < 4; j++) {
        a0[j] = 0ull;
        #pragma unroll
        for (int d = 0; d < 3; d++) { a1[j][d] = 0ull; a2[j][d] = 0ull; }
    }

    const float* wp[5] = {w000, w110, w011, w101, w111};

    for (int v = 0; v < 32; v++) {
        // prefetch weight slices for this v (global/L2, before barrier)
        float4 wr[5];
        #pragma unroll
        for (int m = 0; m < 5; m++)
            wr[m] = *(const float4*)(wp[m] + pm * 1024 + v * 32 + wq * 4);

        if (v) __syncthreads();   // prior readers of cbuf/wbuf done

        #pragma unroll
        for (int m = 0; m < 5; m++)
            wbuf[(m * 32 + pm) * 8 + wq] = wr[m];

        // ---- coefficient planes for this v: u = warp+8k, pair p = lane ----
        {
            int p = lane;
            float2 bs = *(const float2*)&s2_s[v * STR + 2 * p];
            float2 b0 = *(const float2*)&v2_s[(v * 3 + 0) * STR + 2 * p];
            float2 b1 = *(const float2*)&v2_s[(v * 3 + 1) * STR + 2 * p];
            float2 b2 = *(const float2*)&v2_s[(v * 3 + 2) * STR + 2 * p];
            #pragma unroll
            for (int k = 0; k < 4; k++) {
                int u = warp + 8 * k;
                float2 as = *(const float2*)&x1s_s[u * STR + 2 * p];
                float2 u0 = *(const float2*)&x1v_s[(u * 3 + 0) * STR + 2 * p];
                float2 u1 = *(const float2*)&x1v_s[(u * 3 + 1) * STR + 2 * p];
                float2 u2 = *(const float2*)&x1v_s[(u * 3 + 2) * STR + 2 * p];
                int ci = u * 32 + p;
                cbuf[            ci] = pack2f(as.x * bs.x, as.y * bs.y);
                cbuf[ 1024     + ci] = pack2f(R3 * (u0.x * b0.x + u1.x * b1.x + u2.x * b2.x),
                                              R3 * (u0.y * b0.y + u1.y * b1.y + u2.y * b2.y));
                cbuf[ 2 * 1024 + ci] = pack2f(as.x * b0.x, as.y * b0.y);
                cbuf[ 3 * 1024 + ci] = pack2f(as.x * b1.x, as.y * b1.y);
                cbuf[ 4 * 1024 + ci] = pack2f(as.x * b2.x, as.y * b2.y);
                cbuf[ 5 * 1024 + ci] = pack2f(u0.x * bs.x, u0.y * bs.y);
                cbuf[ 6 * 1024 + ci] = pack2f(u1.x * bs.x, u1.y * bs.y);
                cbuf[ 7 * 1024 + ci] = pack2f(u2.x * bs.x, u2.y * bs.y);
                cbuf[ 8 * 1024 + ci] = pack2f(u1.x * b2.x - u2.x * b1.x,
                                              u1.y * b2.y - u2.y * b1.y);
                cbuf[ 9 * 1024 + ci] = pack2f(u2.x * b0.x - u0.x * b2.x,
                                              u2.y * b0.y - u0.y * b2.y);
                cbuf[10 * 1024 + ci] = pack2f(u0.x * b1.x - u1.x * b0.x,
                                              u0.y * b1.y - u1.y * b0.y);
            }
        }
        __syncthreads();

        // ---- main accumulation over u ----
        #pragma unroll 2
        for (int u = 0; u < 32; u++) {
            const ull* cb = cbuf + u * 32 + pm;
            ull c000 = cb[0], c110 = cb[1024];
            ull c011[3] = {cb[2048], cb[3072], cb[4096]};
            ull c101[3] = {cb[5120], cb[6144], cb[7168]};
            ull c111[3] = {cb[8192], cb[9216], cb[10240]};
            const float4* wb = wbuf + u * 8 + wq;
            float4 W0 = wb[0], W1 = wb[256], W2 = wb[512], W3 = wb[768], W4 = wb[1024];
            float f0[4] = {W0.x, W0.y, W0.z, W0.w};
            float f1[4] = {W1.x, W1.y, W1.z, W1.w};
            float f2[4] = {W2.x, W2.y, W2.z, W2.w};
            float f3[4] = {W3.x, W3.y, W3.z, W3.w};
            float f4[4] = {W4.x, W4.y, W4.z, W4.w};
            #pragma unroll
            for (int j = 0; j < 4; j++) {
                ull d0 = pack2f(f0[j], f0[j]), d1 = pack2f(f1[j], f1[j]);
                ull d2 = pack2f(f2[j], f2[j]), d3 = pack2f(f3[j], f3[j]);
                ull d4 = pack2f(f4[j], f4[j]);
                fma2(a0[j], c000, d0);
                fma2(a0[j], c110, d1);
                #pragma unroll
                for (int d = 0; d < 3; d++) {
                    fma2(a1[j][d], c011[d], d2);
                    fma2(a1[j][d], c101[d], d3);
                    fma2(a2[j][d], c111[d], d4);
                }
            }
        }
    }

    // ---- store: rows 2*pm, 2*pm+1; w = 4*wq..4*wq+3 ----
    #pragma unroll
    for (int r = 0; r < 2; r++) {
        float* o = out + (size_t)(zb + 2 * pm + r) * 224;
        float o0[4], o1[12], o2[12];
        #pragma unroll
        for (int j = 0; j < 4; j++) {
            float2 t = up2(a0[j]); o0[j] = r ? t.y : t.x;
            #pragma unroll
            for (int d = 0; d < 3; d++) {
                float2 t1 = up2(a1[j][d]); o1[j * 3 + d] = r ? t1.y : t1.x;
                float2 t2 = up2(a2[j][d]); o2[j * 3 + d] = r ? t2.y : t2.x;
            }
        }
        ((float4*)o)[wq] = make_float4(o0[0], o0[1], o0[2], o0[3]);
        float4* q1 = (float4*)(o + 32 + 12 * wq);
        q1[0] = make_float4(o1[0], o1[1], o1[2],  o1[3]);
        q1[1] = make_float4(o1[4], o1[5], o1[6],  o1[7]);
        q1[2] = make_float4(o1[8], o1[9], o1[10], o1[11]);
        float4* q2 = (float4*)(o + 128 + 12 * wq);
        q2[0] = make_float4(o2[0], o2[1], o2[2],  o2[3]);
        q2[1] = make_float4(o2[4], o2[5], o2[6],  o2[7]);
        q2[2] = make_float4(o2[8], o2[9], o2[10], o2[11]);
    }
}

extern "C" void kernel_launch(void* const* d_in, const int* in_sizes, int n_in,
                              void* d_out, int out_size) {
    (void)in_sizes; (void)n_in; (void)out_size;
    cudaFuncSetAttribute(tp_kernel, cudaFuncAttributeMaxDynamicSharedMemorySize, SMEM_BYTES);
    tp_kernel<<<NCTA, 256, SMEM_BYTES>>>(
        (const float*)d_in[0],   // x1
        (const float*)d_in[1],   // x2
        (const float*)d_in[2],   // w000
        (const float*)d_in[3],   // w011
        (const float*)d_in[4],   // w101
        (const float*)d_in[5],   // w110
        (const float*)d_in[6],   // w111
        (float*)d_out);
}